// round 8
// baseline (speedup 1.0000x reference)
#include <cuda_runtime.h>

#define Tv 512
#define ROWW 60    // floats per emission smem row (56 data + 4 pad) -> 240B
#define MROWW 12   // ints per mask smem row (8 + 4 pad) -> 48B, conflict-free int4
#define EFLOATS (64 * ROWW)
#define MINTS   (64 * MROWW)
#define SMEM_BYTES (3 * EFLOATS * 4 + 3 * MINTS * 4)

typedef unsigned long long u64;

static __device__ __forceinline__ u64 PK(float a, float b) {
    u64 r; asm("mov.b64 %0,{%1,%2};" : "=l"(r) : "r"(__float_as_uint(a)), "r"(__float_as_uint(b))); return r;
}
static __device__ __forceinline__ void UPK(u64 v, float& a, float& b) {
    unsigned x, y; asm("mov.b64 {%0,%1},%2;" : "=r"(x), "=r"(y) : "l"(v));
    a = __uint_as_float(x); b = __uint_as_float(y);
}
static __device__ __forceinline__ u64 FMA2(u64 a, u64 b, u64 c) {
    u64 d; asm("fma.rn.f32x2 %0,%1,%2,%3;" : "=l"(d) : "l"(a), "l"(b), "l"(c)); return d;
}
static __device__ __forceinline__ u64 MUL2(u64 a, u64 b) {
    u64 d; asm("mul.rn.f32x2 %0,%1,%2;" : "=l"(d) : "l"(a), "l"(b)); return d;
}
static __device__ __forceinline__ void cpa16(void* dst, const void* src) {
    unsigned d = (unsigned)__cvta_generic_to_shared(dst);
    asm volatile("cp.async.cg.shared.global [%0], [%1], 16;" :: "r"(d), "l"(src));
}
#define CP_COMMIT() asm volatile("cp.async.commit_group;")
#define CP_WAIT2()  asm volatile("cp.async.wait_group 2;")

__global__ void __launch_bounds__(256, 1)
crf_kernel(const float* __restrict__ em,
           const int* __restrict__ labels,
           const int* __restrict__ mask,
           const float* __restrict__ startT,
           const float* __restrict__ endT,
           const float* __restrict__ trans,
           float* __restrict__ out)
{
    // ================= numerator CTAs (blocks 128..143) =================
    if (blockIdx.x >= 128) {
        const int gidx = (blockIdx.x - 128) * 256 + threadIdx.x;   // 0..4095
        const int s0 = gidx * 2, s1 = s0 + 1;
        const int4* l40 = (const int4*)(labels + (size_t)s0 * Tv);
        const int4* m40 = (const int4*)(mask   + (size_t)s0 * Tv);
        const int4* l41 = (const int4*)(labels + (size_t)s1 * Tv);
        const int4* m41 = (const int4*)(mask   + (size_t)s1 * Tv);
        const float* e0 = em + (size_t)s0 * (Tv * 7);
        const float* e1 = em + (size_t)s1 * (Tv * 7);

        int4 lc0 = __ldg(l40), mc0 = __ldg(m40);
        int4 lc1 = __ldg(l41), mc1 = __ldg(m41);

        int pv0 = lc0.x < 0 ? 0 : lc0.x;
        int pv1 = lc1.x < 0 ? 0 : lc1.x;
        float n0 = __ldg(startT + pv0) + __ldg(e0 + pv0);
        float n1 = __ldg(startT + pv1) + __ldg(e1 + pv1);

#define NSTEP(NN, PV, LV, MV, EP) do { \
        int _Lc = (LV) < 0 ? 0 : (LV); \
        float _v = __ldg(trans + (PV) * 7 + _Lc) + __ldg((EP) + _Lc); \
        NN += (MV) ? _v : 0.f; \
        PV  = (MV) ? _Lc : PV; } while (0)

        // steps 1..3
        NSTEP(n0, pv0, lc0.y, mc0.y, e0 + 7);  NSTEP(n1, pv1, lc1.y, mc1.y, e1 + 7);
        NSTEP(n0, pv0, lc0.z, mc0.z, e0 + 14); NSTEP(n1, pv1, lc1.z, mc1.z, e1 + 14);
        NSTEP(n0, pv0, lc0.w, mc0.w, e0 + 21); NSTEP(n1, pv1, lc1.w, mc1.w, e1 + 21);

        int4 ln0 = __ldg(l40 + 1), mn0 = __ldg(m40 + 1);
        int4 ln1 = __ldg(l41 + 1), mn1 = __ldg(m41 + 1);
#pragma unroll 1
        for (int g = 1; g < 128; g++) {
            lc0 = ln0; mc0 = mn0; lc1 = ln1; mc1 = mn1;
            if (g < 127) {
                ln0 = __ldg(l40 + g + 1); mn0 = __ldg(m40 + g + 1);
                ln1 = __ldg(l41 + g + 1); mn1 = __ldg(m41 + g + 1);
            }
            const float* p0 = e0 + g * 28;
            const float* p1 = e1 + g * 28;
            NSTEP(n0, pv0, lc0.x, mc0.x, p0);      NSTEP(n1, pv1, lc1.x, mc1.x, p1);
            NSTEP(n0, pv0, lc0.y, mc0.y, p0 + 7);  NSTEP(n1, pv1, lc1.y, mc1.y, p1 + 7);
            NSTEP(n0, pv0, lc0.z, mc0.z, p0 + 14); NSTEP(n1, pv1, lc1.z, mc1.z, p1 + 14);
            NSTEP(n0, pv0, lc0.w, mc0.w, p0 + 21); NSTEP(n1, pv1, lc1.w, mc1.w, p1 + 21);
        }
#undef NSTEP
        float acc = n0 + __ldg(endT + pv0) + n1 + __ldg(endT + pv1);
#pragma unroll
        for (int off = 16; off > 0; off >>= 1)
            acc += __shfl_xor_sync(0xFFFFFFFFu, acc, off);
        if ((threadIdx.x & 31) == 0) atomicAdd(out, -acc);
        return;
    }

    // ================= forward CTAs (blocks 0..127), warp 0 only =================
    if (threadIdx.x >= 32) return;
    extern __shared__ char sbase[];
    float* ES = (float*)sbase;                     // 3 emission stages
    int*   MS = (int*)(sbase + 3 * EFLOATS * 4);   // 3 mask stages

    const int lane = threadIdx.x;
    const int base = blockIdx.x * 64;
    const float* emb  = em + (size_t)base * (Tv * 7);
    const int*   mskb = mask + (size_t)base * Tv;

    u64 EE[7][7];
#pragma unroll
    for (int i = 0; i < 7; i++)
#pragma unroll
        for (int j = 0; j < 7; j++) {
            float e = __expf(__ldg(&trans[i * 7 + j]));
            EE[i][j] = PK(e, e);
        }

#define STAGE(MM) do { \
    float* _eb = ES + ((MM) % 3) * EFLOATS; \
    int*   _mb = MS + ((MM) % 3) * MINTS; \
    _Pragma("unroll") \
    for (int i = 0; i < 28; i++) { \
        int idx = i * 32 + lane; int r = (idx * 4682) >> 16; int c = idx - r * 14; \
        cpa16(_eb + r * ROWW + c * 4, emb + (size_t)r * (Tv * 7) + (MM) * 56 + c * 4); \
    } \
    _Pragma("unroll") \
    for (int i = 0; i < 4; i++) { \
        int idx = i * 32 + lane; int s = idx >> 1; int h = idx & 1; \
        cpa16(_mb + s * MROWW + h * 4, mskb + (size_t)s * Tv + (MM) * 8 + h * 4); \
    } \
    CP_COMMIT(); } while (0)

    u64 p[7];
    int xsA = 0, xsB = 0;

    auto FSTEP = [&](const float* epA, const float* epB) {   // all masks = 1
        u64 q[7];
#pragma unroll
        for (int j = 0; j < 7; j++) q[j] = MUL2(p[0], EE[0][j]);
#pragma unroll
        for (int i = 1; i < 7; i++)
#pragma unroll
            for (int j = 0; j < 7; j++) q[j] = FMA2(p[i], EE[i][j], q[j]);
#pragma unroll
        for (int j = 0; j < 7; j++)
            p[j] = MUL2(q[j], PK(__expf(epA[j]), __expf(epB[j])));
    };
    auto SSTEP = [&](const float* epA, const float* epB, int MA, int MB) {
        u64 q[7];
#pragma unroll
        for (int j = 0; j < 7; j++) q[j] = MUL2(p[0], EE[0][j]);
#pragma unroll
        for (int i = 1; i < 7; i++)
#pragma unroll
            for (int j = 0; j < 7; j++) q[j] = FMA2(p[i], EE[i][j], q[j]);
#pragma unroll
        for (int j = 0; j < 7; j++)
            q[j] = MUL2(q[j], PK(__expf(epA[j]), __expf(epB[j])));
        unsigned mA32 = MA ? 0xFFFFFFFFu : 0u;
        unsigned mB32 = MB ? 0xFFFFFFFFu : 0u;
        u64 mm = ((u64)mB32 << 32) | mA32;
#pragma unroll
        for (int j = 0; j < 7; j++) p[j] = (q[j] & mm) | (p[j] & ~mm);
    };

#define RENORM() do { \
    float aA[7], aB[7]; \
    _Pragma("unroll") for (int j = 0; j < 7; j++) UPK(p[j], aA[j], aB[j]); \
    float mxA = aA[0], mxB = aB[0]; \
    _Pragma("unroll") for (int j = 1; j < 7; j++) { mxA = fmaxf(mxA, aA[j]); mxB = fmaxf(mxB, aB[j]); } \
    int exA = (__float_as_int(mxA) >> 23) & 0xFF; \
    int exB = (__float_as_int(mxB) >> 23) & 0xFF; \
    float invA = __int_as_float((254 - exA) << 23); \
    float invB = __int_as_float((254 - exB) << 23); \
    xsA += exA - 127; xsB += exB - 127; \
    u64 iv = PK(invA, invB); \
    _Pragma("unroll") for (int j = 0; j < 7; j++) p[j] = MUL2(p[j], iv); } while (0)

    // ---- prologue: stage macros 0..2 ----
    STAGE(0); STAGE(1); STAGE(2);
    CP_WAIT2(); __syncwarp();

    // ---- macro 0: init + steps 1..7 ----
    {
        const float* rA = ES + lane * ROWW;
        const float* rB = ES + (lane + 32) * ROWW;
        const int* mA = MS + lane * MROWW;
        const int* mB = MS + (lane + 32) * MROWW;

        float qA[7], qB[7];
#pragma unroll
        for (int j = 0; j < 7; j++) {
            float s = __ldg(startT + j);
            qA[j] = __expf(s + rA[j]);
            qB[j] = __expf(s + rB[j]);
        }
        float mxA = qA[0], mxB = qB[0];
#pragma unroll
        for (int j = 1; j < 7; j++) { mxA = fmaxf(mxA, qA[j]); mxB = fmaxf(mxB, qB[j]); }
        int exA = (__float_as_int(mxA) >> 23) & 0xFF;
        int exB = (__float_as_int(mxB) >> 23) & 0xFF;
        float invA = __int_as_float((254 - exA) << 23);
        float invB = __int_as_float((254 - exB) << 23);
        xsA = exA - 127; xsB = exB - 127;
#pragma unroll
        for (int j = 0; j < 7; j++) p[j] = PK(qA[j] * invA, qB[j] * invB);

        int4 ma0 = *(const int4*)(mA),     ma1 = *(const int4*)(mA + 4);
        int4 mb0 = *(const int4*)(mB),     mb1 = *(const int4*)(mB + 4);
        SSTEP(rA + 7,  rB + 7,  ma0.y, mb0.y);
        SSTEP(rA + 14, rB + 14, ma0.z, mb0.z);
        SSTEP(rA + 21, rB + 21, ma0.w, mb0.w);
        SSTEP(rA + 28, rB + 28, ma1.x, mb1.x);
        SSTEP(rA + 35, rB + 35, ma1.y, mb1.y);
        SSTEP(rA + 42, rB + 42, ma1.z, mb1.z);
        SSTEP(rA + 49, rB + 49, ma1.w, mb1.w);
        RENORM();
    }
    __syncwarp();
    STAGE(3);

    // ---- mainloop: macros 1..63 ----
#pragma unroll 1
    for (int m = 1; m < 64; m++) {
        CP_WAIT2(); __syncwarp();
        int st = m % 3;
        const float* rA = ES + st * EFLOATS + lane * ROWW;
        const float* rB = ES + st * EFLOATS + (lane + 32) * ROWW;
        const int* mA = MS + st * MINTS + lane * MROWW;
        const int* mB = MS + st * MINTS + (lane + 32) * MROWW;
        int4 ma0 = *(const int4*)(mA), ma1 = *(const int4*)(mA + 4);
        int4 mb0 = *(const int4*)(mB), mb1 = *(const int4*)(mB + 4);
        int am = ma0.x & ma0.y & ma0.z & ma0.w & ma1.x & ma1.y & ma1.z & ma1.w
               & mb0.x & mb0.y & mb0.z & mb0.w & mb1.x & mb1.y & mb1.z & mb1.w;
        if (__all_sync(0xFFFFFFFFu, am)) {
#pragma unroll
            for (int s = 0; s < 8; s++) FSTEP(rA + s * 7, rB + s * 7);
        } else {
            SSTEP(rA,      rB,      ma0.x, mb0.x); SSTEP(rA + 7,  rB + 7,  ma0.y, mb0.y);
            SSTEP(rA + 14, rB + 14, ma0.z, mb0.z); SSTEP(rA + 21, rB + 21, ma0.w, mb0.w);
            SSTEP(rA + 28, rB + 28, ma1.x, mb1.x); SSTEP(rA + 35, rB + 35, ma1.y, mb1.y);
            SSTEP(rA + 42, rB + 42, ma1.z, mb1.z); SSTEP(rA + 49, rB + 49, ma1.w, mb1.w);
        }
        RENORM();
        __syncwarp();
        if (m + 3 < 64) STAGE(m + 3);
    }

    // ---- finish: den only ----
    float aA[7], aB[7];
#pragma unroll
    for (int j = 0; j < 7; j++) UPK(p[j], aA[j], aB[j]);
    float accA = 0.f, accB = 0.f;
#pragma unroll
    for (int j = 0; j < 7; j++) {
        float ee = __expf(__ldg(endT + j));
        accA = fmaf(aA[j], ee, accA);
        accB = fmaf(aB[j], ee, accB);
    }
    const float LN2 = 0.69314718055994531f;
    float r = (__logf(accA) + (float)xsA * LN2) + (__logf(accB) + (float)xsB * LN2);
#pragma unroll
    for (int off = 16; off > 0; off >>= 1)
        r += __shfl_xor_sync(0xFFFFFFFFu, r, off);
    if (lane == 0) atomicAdd(out, r);

#undef STAGE
#undef RENORM
}

extern "C" void kernel_launch(void* const* d_in, const int* in_sizes, int n_in,
                              void* d_out, int out_size)
{
    const float* em     = (const float*)d_in[0];
    const int*   labels = (const int*)  d_in[1];
    const int*   mask   = (const int*)  d_in[2];
    const float* startT = (const float*)d_in[3];
    const float* endT   = (const float*)d_in[4];
    const float* trans  = (const float*)d_in[5];

    cudaFuncSetAttribute(crf_kernel, cudaFuncAttributeMaxDynamicSharedMemorySize, SMEM_BYTES);
    cudaMemsetAsync(d_out, 0, sizeof(float));
    crf_kernel<<<144, 256, SMEM_BYTES>>>(em, labels, mask, startT, endT, trans, (float*)d_out);
}

// round 9
// speedup vs baseline: 1.8761x; 1.8761x over previous
#include <cuda_runtime.h>

#define Tv 512
#define ROWW 60    // floats per emission smem row (56 data + 4 pad) -> 240B
#define MROWW 12   // ints per label/mask smem row (8 + 4 pad)
#define EFLOATS (64 * ROWW)
#define MINTS   (64 * MROWW)

// ---- smem layout (bytes) ----
#define OFF_ES   0
#define SZ_ES    (2 * 3 * EFLOATS * 4)
#define OFF_MS   (OFF_ES + SZ_ES)
#define SZ_MS    (2 * 3 * MINTS * 4)
#define OFF_LS   (OFF_MS + SZ_MS)
#define SZ_LS    (2 * 3 * MINTS * 4)
#define OFF_APUB (OFF_LS + SZ_LS)
#define OFF_BPUB (OFF_APUB + 64 * 8 * 4)
#define OFF_AX   (OFF_BPUB + 64 * 8 * 4)
#define OFF_BX   (OFF_AX + 256)
#define OFF_NUMF (OFF_BX + 256)
#define OFF_NUMB (OFF_NUMF + 256)
#define OFF_CF   (OFF_NUMB + 256)
#define OFF_CB   (OFF_CF + 256)
#define OFF_STR  (OFF_CB + 256)
#define SMEM_BYTES (OFF_STR + 256)

typedef unsigned long long u64;

static __device__ __forceinline__ u64 PK(float a, float b) {
    u64 r; asm("mov.b64 %0,{%1,%2};" : "=l"(r) : "r"(__float_as_uint(a)), "r"(__float_as_uint(b))); return r;
}
static __device__ __forceinline__ void UPK(u64 v, float& a, float& b) {
    unsigned x, y; asm("mov.b64 {%0,%1},%2;" : "=r"(x), "=r"(y) : "l"(v));
    a = __uint_as_float(x); b = __uint_as_float(y);
}
static __device__ __forceinline__ u64 FMA2(u64 a, u64 b, u64 c) {
    u64 d; asm("fma.rn.f32x2 %0,%1,%2,%3;" : "=l"(d) : "l"(a), "l"(b), "l"(c)); return d;
}
static __device__ __forceinline__ u64 MUL2(u64 a, u64 b) {
    u64 d; asm("mul.rn.f32x2 %0,%1,%2;" : "=l"(d) : "l"(a), "l"(b)); return d;
}
static __device__ __forceinline__ void cpa16(void* dst, const void* src) {
    unsigned d = (unsigned)__cvta_generic_to_shared(dst);
    asm volatile("cp.async.cg.shared.global [%0], [%1], 16;" :: "r"(d), "l"(src));
}
#define CP_COMMIT() asm volatile("cp.async.commit_group;")
#define CP_WAIT2()  asm volatile("cp.async.wait_group 2;")

__global__ void __launch_bounds__(64, 1)
crf_kernel(const float* __restrict__ em,
           const int* __restrict__ labels,
           const int* __restrict__ mask,
           const float* __restrict__ startT,
           const float* __restrict__ endT,
           const float* __restrict__ trans,
           float* __restrict__ out)
{
    extern __shared__ char sb[];
    float* STR = (float*)(sb + OFF_STR);

    const int tid  = threadIdx.x;
    const int wid  = tid >> 5;
    const int lane = tid & 31;

    for (int i = tid; i < 49; i += 64) STR[i] = trans[i];
    __syncthreads();

    const int base = blockIdx.x * 64;
    const float* emb  = em + (size_t)base * (Tv * 7);
    const int*   labb = labels + (size_t)base * Tv;
    const int*   mskb = mask   + (size_t)base * Tv;

    // exp(transitions) as duplicated pairs (shared by both roles)
    u64 EE[7][7];
#pragma unroll
    for (int i = 0; i < 7; i++)
#pragma unroll
        for (int j = 0; j < 7; j++) {
            float e = __expf(__ldg(&trans[i * 7 + j]));
            EE[i][j] = PK(e, e);
        }

    // per-warp staging buffers
    float* ESW = (float*)(sb + OFF_ES) + wid * 3 * EFLOATS;
    int*   MSW = (int*)(sb + OFF_MS) + wid * 3 * MINTS;
    int*   LSW = (int*)(sb + OFF_LS) + wid * 3 * MINTS;

#define STAGE(SLOT, MM) do { \
    float* _eb = ESW + (SLOT) * EFLOATS; \
    int*   _mb = MSW + (SLOT) * MINTS; \
    int*   _lb = LSW + (SLOT) * MINTS; \
    _Pragma("unroll") \
    for (int i = 0; i < 28; i++) { \
        int idx = i * 32 + lane; int r = (idx * 4682) >> 16; int c = idx - r * 14; \
        cpa16(_eb + r * ROWW + c * 4, emb + (size_t)r * (Tv * 7) + (MM) * 56 + c * 4); \
    } \
    _Pragma("unroll") \
    for (int i = 0; i < 4; i++) { \
        int idx = i * 32 + lane; int s = idx >> 1; int h = idx & 1; \
        cpa16(_mb + s * MROWW + h * 4, mskb + (size_t)s * Tv + (MM) * 8 + h * 4); \
        cpa16(_lb + s * MROWW + h * 4, labb + (size_t)s * Tv + (MM) * 8 + h * 4); \
    } \
    CP_COMMIT(); } while (0)

    u64 p[7];                  // state (fwd: alpha, bwd: beta), (seqA,seqB) pairs
    int xsA = 0, xsB = 0;

#define RENORM() do { \
    float aA[7], aB[7]; \
    _Pragma("unroll") for (int j = 0; j < 7; j++) UPK(p[j], aA[j], aB[j]); \
    float mxA = aA[0], mxB = aB[0]; \
    _Pragma("unroll") for (int j = 1; j < 7; j++) { mxA = fmaxf(mxA, aA[j]); mxB = fmaxf(mxB, aB[j]); } \
    int exA = (__float_as_int(mxA) >> 23) & 0xFF; \
    int exB = (__float_as_int(mxB) >> 23) & 0xFF; \
    float invA = __int_as_float((254 - exA) << 23); \
    float invB = __int_as_float((254 - exB) << 23); \
    xsA += exA - 127; xsB += exB - 127; \
    u64 iv = PK(invA, invB); \
    _Pragma("unroll") for (int j = 0; j < 7; j++) p[j] = MUL2(p[j], iv); } while (0)

    float numP = 0.f, numQ = 0.f;   // numerator partials (seqA, seqB)
    int   cntP = 0,   cntQ = 0;     // mask counts

    if (wid == 0) {
        // ======================= FORWARD: t in [0,256) =======================
        auto FSTEP = [&](const float* eA, const float* eB) {
            u64 q[7];
#pragma unroll
            for (int j = 0; j < 7; j++) q[j] = MUL2(p[0], EE[0][j]);
#pragma unroll
            for (int i = 1; i < 7; i++)
#pragma unroll
                for (int j = 0; j < 7; j++) q[j] = FMA2(p[i], EE[i][j], q[j]);
#pragma unroll
            for (int j = 0; j < 7; j++)
                p[j] = MUL2(q[j], PK(__expf(eA[j]), __expf(eB[j])));
        };
        auto SSTEP = [&](const float* eA, const float* eB, int MA, int MB) {
            u64 q[7];
#pragma unroll
            for (int j = 0; j < 7; j++) q[j] = MUL2(p[0], EE[0][j]);
#pragma unroll
            for (int i = 1; i < 7; i++)
#pragma unroll
                for (int j = 0; j < 7; j++) q[j] = FMA2(p[i], EE[i][j], q[j]);
#pragma unroll
            for (int j = 0; j < 7; j++)
                q[j] = MUL2(q[j], PK(__expf(eA[j]), __expf(eB[j])));
            u64 mm = ((u64)(MB ? 0xFFFFFFFFu : 0u) << 32) | (MA ? 0xFFFFFFFFu : 0u);
#pragma unroll
            for (int j = 0; j < 7; j++) p[j] = (q[j] & mm) | (p[j] & ~mm);
        };

        STAGE(0, 0); STAGE(1, 1); STAGE(2, 2);
        CP_WAIT2(); __syncwarp();

        int carryA = 0, carryB = 0;   // last label of previous macro (raw-adjacent)
#pragma unroll 1
        for (int m = 0; m < 32; m++) {
            int st = (m % 3);
            const float* rA = ESW + st * EFLOATS + lane * ROWW;
            const float* rB = rA + 32 * ROWW;
            const int* mrA = MSW + st * MINTS + lane * MROWW;
            const int* mrB = mrA + 32 * MROWW;
            const int* lrA = LSW + st * MINTS + lane * MROWW;
            const int* lrB = lrA + 32 * MROWW;
            int4 ma0 = *(const int4*)(mrA), ma1 = *(const int4*)(mrA + 4);
            int4 mb0 = *(const int4*)(mrB), mb1 = *(const int4*)(mrB + 4);
            int mAr[8] = {ma0.x, ma0.y, ma0.z, ma0.w, ma1.x, ma1.y, ma1.z, ma1.w};
            int mBr[8] = {mb0.x, mb0.y, mb0.z, mb0.w, mb1.x, mb1.y, mb1.z, mb1.w};
            int4 la0 = *(const int4*)(lrA), la1 = *(const int4*)(lrA + 4);
            int4 lb0 = *(const int4*)(lrB), lb1 = *(const int4*)(lrB + 4);
            int lAr[8] = {la0.x, la0.y, la0.z, la0.w, la1.x, la1.y, la1.z, la1.w};
            int lBr[8] = {lb0.x, lb0.y, lb0.z, lb0.w, lb1.x, lb1.y, lb1.z, lb1.w};

            // ---- numerator (chain-free; prev is raw adjacent label) ----
#pragma unroll
            for (int s = 0; s < 8; s++) {
                int LA = lAr[s] < 0 ? 0 : lAr[s];
                int LB = lBr[s] < 0 ? 0 : lBr[s];
                if (m == 0 && s == 0) {
                    numP += __ldg(startT + LA) + rA[LA];
                    numQ += __ldg(startT + LB) + rB[LB];
                } else {
                    int PA = (s == 0) ? carryA : (lAr[s-1] < 0 ? 0 : lAr[s-1]);
                    int PB = (s == 0) ? carryB : (lBr[s-1] < 0 ? 0 : lBr[s-1]);
                    float vA = STR[PA * 7 + LA] + rA[s * 7 + LA];
                    float vB = STR[PB * 7 + LB] + rB[s * 7 + LB];
                    numP += mAr[s] ? vA : 0.f;
                    numQ += mBr[s] ? vB : 0.f;
                }
                cntP += mAr[s] ? 1 : 0;
                cntQ += mBr[s] ? 1 : 0;
            }
            carryA = lAr[7] < 0 ? 0 : lAr[7];
            carryB = lBr[7] < 0 ? 0 : lBr[7];

            // ---- recursion ----
            if (m == 0) {
                float qA[7], qB[7];
#pragma unroll
                for (int j = 0; j < 7; j++) {
                    float s0 = __ldg(startT + j);
                    qA[j] = __expf(s0 + rA[j]);
                    qB[j] = __expf(s0 + rB[j]);
                }
                float mxA = qA[0], mxB = qB[0];
#pragma unroll
                for (int j = 1; j < 7; j++) { mxA = fmaxf(mxA, qA[j]); mxB = fmaxf(mxB, qB[j]); }
                int exA = (__float_as_int(mxA) >> 23) & 0xFF;
                int exB = (__float_as_int(mxB) >> 23) & 0xFF;
                float invA = __int_as_float((254 - exA) << 23);
                float invB = __int_as_float((254 - exB) << 23);
                xsA = exA - 127; xsB = exB - 127;
#pragma unroll
                for (int j = 0; j < 7; j++) p[j] = PK(qA[j] * invA, qB[j] * invB);
#pragma unroll
                for (int s = 1; s < 8; s++) SSTEP(rA + s * 7, rB + s * 7, mAr[s], mBr[s]);
                RENORM();
            } else {
                int am = mAr[0]&mAr[1]&mAr[2]&mAr[3]&mAr[4]&mAr[5]&mAr[6]&mAr[7]
                       & mBr[0]&mBr[1]&mBr[2]&mBr[3]&mBr[4]&mBr[5]&mBr[6]&mBr[7];
                if (__all_sync(0xFFFFFFFFu, am)) {
#pragma unroll
                    for (int s = 0; s < 8; s++) FSTEP(rA + s * 7, rB + s * 7);
                } else {
#pragma unroll
                    for (int s = 0; s < 8; s++) SSTEP(rA + s * 7, rB + s * 7, mAr[s], mBr[s]);
                }
                RENORM();
            }
            __syncwarp();
            if (m + 3 < 32) STAGE((m + 3) % 3, m + 3);
        }

        // ---- publish alpha ----
        float aA[7], aB[7];
#pragma unroll
        for (int j = 0; j < 7; j++) UPK(p[j], aA[j], aB[j]);
        float* AP = (float*)(sb + OFF_APUB);
        int*   AX = (int*)(sb + OFF_AX);
        float* NF = (float*)(sb + OFF_NUMF);
        int*   CF = (int*)(sb + OFF_CF);
#pragma unroll
        for (int j = 0; j < 7; j++) { AP[lane * 8 + j] = aA[j]; AP[(lane + 32) * 8 + j] = aB[j]; }
        AX[lane] = xsA; AX[lane + 32] = xsB;
        NF[lane] = numP; NF[lane + 32] = numQ;
        CF[lane] = cntP; CF[lane + 32] = cntQ;
        __syncthreads();

        // ---- combine (warp 0) ----
        const float* BP = (const float*)(sb + OFF_BPUB);
        const int*   BX = (const int*)(sb + OFF_BX);
        const float* NB = (const float*)(sb + OFF_NUMB);
        const int*   CB = (const int*)(sb + OFF_CB);
        const float LN2 = 0.69314718055994531f;
        float r = 0.f;
#pragma unroll
        for (int k = 0; k < 2; k++) {
            int seq = lane + k * 32;
            float acc = 0.f;
#pragma unroll
            for (int j = 0; j < 7; j++) acc = fmaf(AP[seq * 8 + j], BP[seq * 8 + j], acc);
            float den = __logf(acc) + (float)(AX[seq] + BX[seq]) * LN2;
            int cnt = CF[seq] + CB[seq];
            int lastIdx = cnt > 0 ? cnt - 1 : Tv - 1;
            int lt = __ldg(labb + (size_t)seq * Tv + lastIdx);
            lt = lt < 0 ? 0 : lt;
            float num = NF[seq] + NB[seq] + __ldg(endT + lt);
            r += den - num;
        }
#pragma unroll
        for (int off = 16; off > 0; off >>= 1)
            r += __shfl_xor_sync(0xFFFFFFFFu, r, off);
        if (lane == 0) atomicAdd(out, r);

    } else {
        // ======================= BACKWARD: t in [256,512) =======================
        auto BFSTEP = [&](const float* eA, const float* eB) {
            u64 w[7];
#pragma unroll
            for (int j = 0; j < 7; j++)
                w[j] = MUL2(p[j], PK(__expf(eA[j]), __expf(eB[j])));
            u64 q[7];
#pragma unroll
            for (int i = 0; i < 7; i++) q[i] = MUL2(w[0], EE[i][0]);
#pragma unroll
            for (int j = 1; j < 7; j++)
#pragma unroll
                for (int i = 0; i < 7; i++) q[i] = FMA2(w[j], EE[i][j], q[i]);
#pragma unroll
            for (int i = 0; i < 7; i++) p[i] = q[i];
        };
        auto BSSTEP = [&](const float* eA, const float* eB, int MA, int MB) {
            u64 w[7];
#pragma unroll
            for (int j = 0; j < 7; j++)
                w[j] = MUL2(p[j], PK(__expf(eA[j]), __expf(eB[j])));
            u64 q[7];
#pragma unroll
            for (int i = 0; i < 7; i++) q[i] = MUL2(w[0], EE[i][0]);
#pragma unroll
            for (int j = 1; j < 7; j++)
#pragma unroll
                for (int i = 0; i < 7; i++) q[i] = FMA2(w[j], EE[i][j], q[i]);
            u64 mm = ((u64)(MB ? 0xFFFFFFFFu : 0u) << 32) | (MA ? 0xFFFFFFFFu : 0u);
#pragma unroll
            for (int i = 0; i < 7; i++) p[i] = (q[i] & mm) | (p[i] & ~mm);
        };

        // boundary labels t=255 (closing the last pending cross term)
        int L255A = __ldg(labb + (size_t)lane * Tv + 255);
        int L255B = __ldg(labb + (size_t)(lane + 32) * Tv + 255);
        L255A = L255A < 0 ? 0 : L255A;
        L255B = L255B < 0 ? 0 : L255B;

        // init beta = exp(end)
#pragma unroll
        for (int j = 0; j < 7; j++) { float e = __expf(__ldg(endT + j)); p[j] = PK(e, e); }

        STAGE(0, 63); STAGE(1, 62); STAGE(2, 61);
        CP_WAIT2(); __syncwarp();

        int pendLA = 0, pendMA = 0, pendLB = 0, pendMB = 0;  // macro-boundary cross terms
#pragma unroll 1
        for (int k = 0; k < 32; k++) {
            int st = (k % 3);
            const float* rA = ESW + st * EFLOATS + lane * ROWW;
            const float* rB = rA + 32 * ROWW;
            const int* mrA = MSW + st * MINTS + lane * MROWW;
            const int* mrB = mrA + 32 * MROWW;
            const int* lrA = LSW + st * MINTS + lane * MROWW;
            const int* lrB = lrA + 32 * MROWW;
            int4 ma0 = *(const int4*)(mrA), ma1 = *(const int4*)(mrA + 4);
            int4 mb0 = *(const int4*)(mrB), mb1 = *(const int4*)(mrB + 4);
            int mAr[8] = {ma0.x, ma0.y, ma0.z, ma0.w, ma1.x, ma1.y, ma1.z, ma1.w};
            int mBr[8] = {mb0.x, mb0.y, mb0.z, mb0.w, mb1.x, mb1.y, mb1.z, mb1.w};
            int4 la0 = *(const int4*)(lrA), la1 = *(const int4*)(lrA + 4);
            int4 lb0 = *(const int4*)(lrB), lb1 = *(const int4*)(lrB + 4);
            int lAr[8] = {la0.x, la0.y, la0.z, la0.w, la1.x, la1.y, la1.z, la1.w};
            int lBr[8] = {lb0.x, lb0.y, lb0.z, lb0.w, lb1.x, lb1.y, lb1.z, lb1.w};

            // ---- numerator: internal terms s=1..7 ----
#pragma unroll
            for (int s = 1; s < 8; s++) {
                int LA = lAr[s] < 0 ? 0 : lAr[s];
                int LB = lBr[s] < 0 ? 0 : lBr[s];
                int PA = lAr[s-1] < 0 ? 0 : lAr[s-1];
                int PB = lBr[s-1] < 0 ? 0 : lBr[s-1];
                float vA = STR[PA * 7 + LA] + rA[s * 7 + LA];
                float vB = STR[PB * 7 + LB] + rB[s * 7 + LB];
                numP += mAr[s] ? vA : 0.f;
                numQ += mBr[s] ? vB : 0.f;
                cntP += mAr[s] ? 1 : 0;
                cntQ += mBr[s] ? 1 : 0;
            }
            // close pending cross term from the macro after this one (uses l[7])
            {
                int E7A = lAr[7] < 0 ? 0 : lAr[7];
                int E7B = lBr[7] < 0 ? 0 : lBr[7];
                numP += pendMA ? STR[E7A * 7 + pendLA] : 0.f;
                numQ += pendMB ? STR[E7B * 7 + pendLB] : 0.f;
            }
            // s=0: emission part now; trans part pends on previous macro's l[7]
            {
                int LA = lAr[0] < 0 ? 0 : lAr[0];
                int LB = lBr[0] < 0 ? 0 : lBr[0];
                numP += mAr[0] ? rA[LA] : 0.f;
                numQ += mBr[0] ? rB[LB] : 0.f;
                cntP += mAr[0] ? 1 : 0;
                cntQ += mBr[0] ? 1 : 0;
                pendLA = LA; pendMA = mAr[0];
                pendLB = LB; pendMB = mBr[0];
            }

            // ---- recursion (descending steps) ----
            int am = mAr[0]&mAr[1]&mAr[2]&mAr[3]&mAr[4]&mAr[5]&mAr[6]&mAr[7]
                   & mBr[0]&mBr[1]&mBr[2]&mBr[3]&mBr[4]&mBr[5]&mBr[6]&mBr[7];
            if (__all_sync(0xFFFFFFFFu, am)) {
#pragma unroll
                for (int s = 7; s >= 0; s--) BFSTEP(rA + s * 7, rB + s * 7);
            } else {
#pragma unroll
                for (int s = 7; s >= 0; s--) BSSTEP(rA + s * 7, rB + s * 7, mAr[s], mBr[s]);
            }
            RENORM();
            __syncwarp();
            if (k + 3 < 32) STAGE((k + 3) % 3, 63 - (k + 3));
        }

        // close the final pending term against boundary label t=255
        numP += pendMA ? STR[L255A * 7 + pendLA] : 0.f;
        numQ += pendMB ? STR[L255B * 7 + pendLB] : 0.f;

        // ---- publish beta ----
        float aA[7], aB[7];
#pragma unroll
        for (int j = 0; j < 7; j++) UPK(p[j], aA[j], aB[j]);
        float* BP = (float*)(sb + OFF_BPUB);
        int*   BX = (int*)(sb + OFF_BX);
        float* NB = (float*)(sb + OFF_NUMB);
        int*   CB = (int*)(sb + OFF_CB);
#pragma unroll
        for (int j = 0; j < 7; j++) { BP[lane * 8 + j] = aA[j]; BP[(lane + 32) * 8 + j] = aB[j]; }
        BX[lane] = xsA; BX[lane + 32] = xsB;
        NB[lane] = numP; NB[lane + 32] = numQ;
        CB[lane] = cntP; CB[lane + 32] = cntQ;
        __syncthreads();
    }

#undef STAGE
#undef RENORM
}

extern "C" void kernel_launch(void* const* d_in, const int* in_sizes, int n_in,
                              void* d_out, int out_size)
{
    const float* em     = (const float*)d_in[0];
    const int*   labels = (const int*)  d_in[1];
    const int*   mask   = (const int*)  d_in[2];
    const float* startT = (const float*)d_in[3];
    const float* endT   = (const float*)d_in[4];
    const float* trans  = (const float*)d_in[5];

    cudaFuncSetAttribute(crf_kernel, cudaFuncAttributeMaxDynamicSharedMemorySize, SMEM_BYTES);
    cudaMemsetAsync(d_out, 0, sizeof(float));
    crf_kernel<<<128, 64, SMEM_BYTES>>>(em, labels, mask, startT, endT, trans, (float*)d_out);
}